// round 3
// baseline (speedup 1.0000x reference)
#include <cuda_runtime.h>
#include <mma.h>
#include <cstdint>

using namespace nvcuda;

// ---------------- problem constants ----------------
constexpr int Bz  = 2;
constexpr int Ss  = 2048;
constexpr int HID = 2048;
constexpr int Hh  = 16;
constexpr int KVh = 8;
constexpr int Dd  = 128;
constexpr int MROWS = Bz * Ss;                 // 4096
constexpr int NQKV  = (Hh + 2 * KVh) * Dd;     // 4096
constexpr float SCALE_Q = 0.08838834764831845f; // 1/sqrt(128)

// ---------------- scratch (static device memory; no allocation allowed) ----
__device__ float g_xh[MROWS * HID];
__device__ float g_xl[MROWS * HID];
__device__ float g_wh[NQKV * HID];
__device__ float g_wl[NQKV * HID];
__device__ float g_owh[HID * Hh * Dd];
__device__ float g_owl[HID * Hh * Dd];
__device__ float g_qkv[(size_t)MROWS * NQKV];
__device__ float g_qh[Bz * Hh * Ss * Dd];
__device__ float g_ql[Bz * Hh * Ss * Dd];
__device__ float g_kh[Bz * KVh * Ss * Dd];
__device__ float g_kl[Bz * KVh * Ss * Dd];
__device__ float g_vh[Bz * KVh * Ss * Dd];
__device__ float g_vl[Bz * KVh * Ss * Dd];
__device__ float g_sc[(size_t)Bz * Hh * Ss * Ss];   // scores / attn in-place (537 MB)
__device__ float g_ao[(size_t)MROWS * Hh * Dd];
__device__ float g_aoh[(size_t)MROWS * Hh * Dd];
__device__ float g_aol[(size_t)MROWS * Hh * Dd];

// ---------------- helpers ----------------
__device__ __forceinline__ float tf32r(float x) {
    float r;
    asm("cvt.rna.tf32.f32 %0, %1;" : "=f"(r) : "f"(x));
    return r;
}

__device__ __forceinline__ void wsplit(float* __restrict__ hi, float* __restrict__ lo,
                                       long long idx, float v) {
    float h = tf32r(v);
    hi[idx] = h;
    lo[idx] = tf32r(v - h);
}

// ---------------- split kernel: fp32 -> (tf32 hi, tf32 lo) -----------------
__global__ void k_split(const float* __restrict__ src, float* __restrict__ hi,
                        float* __restrict__ lo, int n4) {
    int i = blockIdx.x * blockDim.x + threadIdx.x;
    if (i >= n4) return;
    float4 v = reinterpret_cast<const float4*>(src)[i];
    float4 h, l;
    h.x = tf32r(v.x); l.x = tf32r(v.x - h.x);
    h.y = tf32r(v.y); l.y = tf32r(v.y - h.y);
    h.z = tf32r(v.z); l.z = tf32r(v.z - h.z);
    h.w = tf32r(v.w); l.w = tf32r(v.w - h.w);
    reinterpret_cast<float4*>(hi)[i] = h;
    reinterpret_cast<float4*>(lo)[i] = l;
}

// ---------------- generic batched 3xTF32 GEMM ------------------------------
// C[m,n] = sum_k A[m,k] * B'[n,k]
//   BNT=true : B stored [N,K] row-major
//   BNT=false: B stored [K,N] row-major (transposed into smem on load)
// ALO/BLO: include the "lo" split term for A / B.
// causal: 0 none; 1 skip tiles with n0>m0 (scores); 2 trim K loop to m0+64 (AV).
// Batch bases: A += b*aSB + h*aSH ; B += b*bSB + (h/gqa)*bSH ; C += b*cSB + h*cSH
// Requires: M,N multiples of 64; K multiple of 32; all pointers 16B aligned.
template <bool ALO, bool BLO, bool BNT>
__global__ void k_gemm3(const float* __restrict__ Ah, const float* __restrict__ Al,
                        const float* __restrict__ Bh, const float* __restrict__ Bl,
                        float* __restrict__ C,
                        int M, int N, int K, int ldc,
                        long long aSB, long long aSH, long long bSB, long long bSH,
                        long long cSB, long long cSH,
                        int Hdim, int gqa, int causal) {
    const int m0 = blockIdx.y * 64;
    const int n0 = blockIdx.x * 64;
    if (causal == 1 && n0 > m0) return;

    const int z = blockIdx.z;
    const int b = z / Hdim;
    const int h = z - b * Hdim;
    const long long aOff = (long long)b * aSB + (long long)h * aSH;
    const long long bOff = (long long)b * bSB + (long long)(h / gqa) * bSH;
    const float* pAh = Ah + aOff;
    const float* pAl = ALO ? (Al + aOff) : nullptr;
    const float* pBh = Bh + bOff;
    const float* pBl = BLO ? (Bl + bOff) : nullptr;
    float* pC = C + (long long)b * cSB + (long long)h * cSH;

    __shared__ float sAh[64][40];
    __shared__ float sBh[64][40];
    __shared__ float sAl[ALO ? 64 : 1][40];
    __shared__ float sBl[BLO ? 64 : 1][40];

    const int tid = threadIdx.x;
    const int wid = tid >> 5;
    const int wm = (wid >> 1) * 32;
    const int wn = (wid & 1) * 32;

    wmma::fragment<wmma::accumulator, 16, 16, 8, float> acc[2][2];
#pragma unroll
    for (int i = 0; i < 2; i++)
#pragma unroll
        for (int j = 0; j < 2; j++) wmma::fill_fragment(acc[i][j], 0.0f);

    const int Kend = (causal == 2) ? (m0 + 64) : K;

    for (int kk = 0; kk < Kend; kk += 32) {
        // A tile: 64 x 32
#pragma unroll
        for (int i = 0; i < 4; i++) {
            int idx = i * 128 + tid;
            int r = idx >> 3, c = (idx & 7) << 2;
            *(float4*)&sAh[r][c] =
                *(const float4*)&pAh[(long long)(m0 + r) * K + kk + c];
            if constexpr (ALO)
                *(float4*)&sAl[r][c] =
                    *(const float4*)&pAl[(long long)(m0 + r) * K + kk + c];
        }
        // B tile: stored as [n][k] in smem
        if constexpr (BNT) {
#pragma unroll
            for (int i = 0; i < 4; i++) {
                int idx = i * 128 + tid;
                int r = idx >> 3, c = (idx & 7) << 2;
                *(float4*)&sBh[r][c] =
                    *(const float4*)&pBh[(long long)(n0 + r) * K + kk + c];
                if constexpr (BLO)
                    *(float4*)&sBl[r][c] =
                        *(const float4*)&pBl[(long long)(n0 + r) * K + kk + c];
            }
        } else {
#pragma unroll
            for (int i = 0; i < 4; i++) {
                int idx = i * 128 + tid;
                int r = idx >> 4, c = (idx & 15) << 2;
                float4 v = *(const float4*)&pBh[(long long)(kk + r) * N + n0 + c];
                sBh[c + 0][r] = v.x; sBh[c + 1][r] = v.y;
                sBh[c + 2][r] = v.z; sBh[c + 3][r] = v.w;
                if constexpr (BLO) {
                    float4 w = *(const float4*)&pBl[(long long)(kk + r) * N + n0 + c];
                    sBl[c + 0][r] = w.x; sBl[c + 1][r] = w.y;
                    sBl[c + 2][r] = w.z; sBl[c + 3][r] = w.w;
                }
            }
        }
        __syncthreads();

#pragma unroll
        for (int ks = 0; ks < 4; ks++) {
            const int k = ks * 8;
            wmma::fragment<wmma::matrix_a, 16, 16, 8, wmma::precision::tf32,
                           wmma::row_major> ah[2], al[2];
            wmma::fragment<wmma::matrix_b, 16, 16, 8, wmma::precision::tf32,
                           wmma::col_major> bh[2], bl[2];
#pragma unroll
            for (int i = 0; i < 2; i++) {
                wmma::load_matrix_sync(ah[i], &sAh[wm + 16 * i][k], 40);
                if constexpr (ALO) wmma::load_matrix_sync(al[i], &sAl[wm + 16 * i][k], 40);
                wmma::load_matrix_sync(bh[i], &sBh[wn + 16 * i][k], 40);
                if constexpr (BLO) wmma::load_matrix_sync(bl[i], &sBl[wn + 16 * i][k], 40);
            }
#pragma unroll
            for (int i = 0; i < 2; i++)
#pragma unroll
                for (int j = 0; j < 2; j++) {
                    if constexpr (ALO) wmma::mma_sync(acc[i][j], al[i], bh[j], acc[i][j]);
                    if constexpr (BLO) wmma::mma_sync(acc[i][j], ah[i], bl[j], acc[i][j]);
                    wmma::mma_sync(acc[i][j], ah[i], bh[j], acc[i][j]);
                }
        }
        __syncthreads();
    }

#pragma unroll
    for (int i = 0; i < 2; i++)
#pragma unroll
        for (int j = 0; j < 2; j++)
            wmma::store_matrix_sync(
                &pC[(long long)(m0 + wm + 16 * i) * ldc + (n0 + wn + 16 * j)],
                acc[i][j], ldc, wmma::mem_row_major);
}

// ---------------- QKV post: RMSNorm + RoPE + tf32 split ---------------------
// One warp per head-vector. Tasks: [0,65536) Q; [65536,98304) K; [98304,131072) V.
__global__ void k_qkvpost(const float* __restrict__ qkv, const float* __restrict__ pe,
                          const float* __restrict__ qnw, const float* __restrict__ knw,
                          float* __restrict__ qh, float* __restrict__ ql,
                          float* __restrict__ kh, float* __restrict__ kl,
                          float* __restrict__ vh, float* __restrict__ vl) {
    const int task = blockIdx.x * 4 + (threadIdx.x >> 5);
    const int lane = threadIdx.x & 31;

    if (task < 65536) {  // ---- Q ----
        const int bs = task >> 4, h = task & 15;
        const float* src = qkv + (long long)bs * NQKV + h * Dd;
        float x0 = src[lane], x1 = src[lane + 32], x2 = src[lane + 64], x3 = src[lane + 96];
        float ss = x0 * x0 + x1 * x1 + x2 * x2 + x3 * x3;
#pragma unroll
        for (int o = 16; o; o >>= 1) ss += __shfl_xor_sync(0xffffffffu, ss, o);
        float inv = rsqrtf(ss * (1.0f / 128.0f) + 1e-6f);
        float n0 = x0 * inv * qnw[lane];
        float n1 = x1 * inv * qnw[lane + 32];
        float n2 = x2 * inv * qnw[lane + 64];
        float n3 = x3 * inv * qnw[lane + 96];
        const float* per = pe + (long long)bs * Dd;
        float c0 = per[lane],      s0 = per[64 + lane];
        float c1 = per[32 + lane], s1 = per[96 + lane];
        float o0 = (n0 * c0 - n2 * s0) * SCALE_Q;   // d = lane
        float o1 = (n1 * c1 - n3 * s1) * SCALE_Q;   // d = lane+32
        float o2 = (n0 * s0 + n2 * c0) * SCALE_Q;   // d = lane+64
        float o3 = (n1 * s1 + n3 * c1) * SCALE_Q;   // d = lane+96
        const int b = bs >> 11, s = bs & 2047;
        long long base = ((long long)(b * Hh + h) * Ss + s) * Dd;
        wsplit(qh, ql, base + lane,      o0);
        wsplit(qh, ql, base + lane + 32, o1);
        wsplit(qh, ql, base + lane + 64, o2);
        wsplit(qh, ql, base + lane + 96, o3);
    } else if (task < 98304) {  // ---- K ----
        const int t = task - 65536;
        const int bs = t >> 3, kvh = t & 7;
        const float* src = qkv + (long long)bs * NQKV + Hh * Dd + kvh * Dd;
        float x0 = src[lane], x1 = src[lane + 32], x2 = src[lane + 64], x3 = src[lane + 96];
        float ss = x0 * x0 + x1 * x1 + x2 * x2 + x3 * x3;
#pragma unroll
        for (int o = 16; o; o >>= 1) ss += __shfl_xor_sync(0xffffffffu, ss, o);
        float inv = rsqrtf(ss * (1.0f / 128.0f) + 1e-6f);
        float n0 = x0 * inv * knw[lane];
        float n1 = x1 * inv * knw[lane + 32];
        float n2 = x2 * inv * knw[lane + 64];
        float n3 = x3 * inv * knw[lane + 96];
        const float* per = pe + (long long)bs * Dd;
        float c0 = per[lane],      s0 = per[64 + lane];
        float c1 = per[32 + lane], s1 = per[96 + lane];
        float o0 = n0 * c0 - n2 * s0;
        float o1 = n1 * c1 - n3 * s1;
        float o2 = n0 * s0 + n2 * c0;
        float o3 = n1 * s1 + n3 * c1;
        const int b = bs >> 11, s = bs & 2047;
        long long base = ((long long)(b * KVh + kvh) * Ss + s) * Dd;
        wsplit(kh, kl, base + lane,      o0);
        wsplit(kh, kl, base + lane + 32, o1);
        wsplit(kh, kl, base + lane + 64, o2);
        wsplit(kh, kl, base + lane + 96, o3);
    } else {  // ---- V ----
        const int t = task - 98304;
        const int bs = t >> 3, kvh = t & 7;
        const float* src = qkv + (long long)bs * NQKV + (Hh + KVh) * Dd + kvh * Dd;
        const int b = bs >> 11, s = bs & 2047;
        long long base = ((long long)(b * KVh + kvh) * Ss + s) * Dd;
        wsplit(vh, vl, base + lane,      src[lane]);
        wsplit(vh, vl, base + lane + 32, src[lane + 32]);
        wsplit(vh, vl, base + lane + 64, src[lane + 64]);
        wsplit(vh, vl, base + lane + 96, src[lane + 96]);
    }
}

// ---------------- causal softmax, in-place, tf32-rounded output -------------
// One block (128 threads) per row (b,h,s). Also zero-fills (s, tile_end) so the
// AV GEMM can read full 64-aligned K chunks.
__global__ void k_softmax(float* __restrict__ sc) {
    const int row = blockIdx.x;  // [0, B*H*S)
    const int s = row & (Ss - 1);
    float* p = sc + (long long)row * Ss;
    const int L = s + 1;
    const int tid = threadIdx.x;

    float ev[16];
    float mx = -3.4e38f;
    int cnt = 0;
    for (int i = tid; i < L; i += 128) {
        float v = p[i];
        ev[cnt++] = v;
        mx = fmaxf(mx, v);
    }
#pragma unroll
    for (int o = 16; o; o >>= 1) mx = fmaxf(mx, __shfl_xor_sync(0xffffffffu, mx, o));
    __shared__ float shm[4], shs[4];
    if ((tid & 31) == 0) shm[tid >> 5] = mx;
    __syncthreads();
    mx = fmaxf(fmaxf(shm[0], shm[1]), fmaxf(shm[2], shm[3]));

    float sum = 0.0f;
    for (int j = 0; j < cnt; j++) {
        float e = __expf(ev[j] - mx);
        ev[j] = e;
        sum += e;
    }
#pragma unroll
    for (int o = 16; o; o >>= 1) sum += __shfl_xor_sync(0xffffffffu, sum, o);
    if ((tid & 31) == 0) shs[tid >> 5] = sum;
    __syncthreads();
    sum = shs[0] + shs[1] + shs[2] + shs[3];
    const float inv = 1.0f / sum;

    cnt = 0;
    for (int i = tid; i < L; i += 128) p[i] = tf32r(ev[cnt++] * inv);
    const int tileEnd = ((s >> 6) << 6) + 64;
    for (int i = L + tid; i < tileEnd; i += 128) p[i] = 0.0f;
}

// ---------------- launch -----------------------------------------------------
extern "C" void kernel_launch(void* const* d_in, const int* in_sizes, int n_in,
                              void* d_out, int out_size) {
    (void)in_sizes; (void)n_in; (void)out_size;
    const float* x   = (const float*)d_in[0];
    const float* pe  = (const float*)d_in[1];
    const float* qw  = (const float*)d_in[2];
    const float* kw  = (const float*)d_in[3];
    const float* vw  = (const float*)d_in[4];
    const float* ow  = (const float*)d_in[5];
    const float* qnw = (const float*)d_in[6];
    const float* knw = (const float*)d_in[7];
    float* out = (float*)d_out;

    float *xh, *xl, *wh, *wl, *owh, *owl, *qkvp;
    float *qh, *ql, *kh, *kl, *vh, *vl, *sc, *ao, *aoh, *aol;
    cudaGetSymbolAddress((void**)&xh, g_xh);
    cudaGetSymbolAddress((void**)&xl, g_xl);
    cudaGetSymbolAddress((void**)&wh, g_wh);
    cudaGetSymbolAddress((void**)&wl, g_wl);
    cudaGetSymbolAddress((void**)&owh, g_owh);
    cudaGetSymbolAddress((void**)&owl, g_owl);
    cudaGetSymbolAddress((void**)&qkvp, g_qkv);
    cudaGetSymbolAddress((void**)&qh, g_qh);
    cudaGetSymbolAddress((void**)&ql, g_ql);
    cudaGetSymbolAddress((void**)&kh, g_kh);
    cudaGetSymbolAddress((void**)&kl, g_kl);
    cudaGetSymbolAddress((void**)&vh, g_vh);
    cudaGetSymbolAddress((void**)&vl, g_vl);
    cudaGetSymbolAddress((void**)&sc, g_sc);
    cudaGetSymbolAddress((void**)&ao, g_ao);
    cudaGetSymbolAddress((void**)&aoh, g_aoh);
    cudaGetSymbolAddress((void**)&aol, g_aol);

    // 1) tf32 splits of x and weights
    {
        int n4 = MROWS * HID / 4;
        k_split<<<(n4 + 255) / 256, 256>>>(x, xh, xl, n4);
    }
    {
        int nq4 = Hh * Dd * HID / 4;
        k_split<<<(nq4 + 255) / 256, 256>>>(qw, wh, wl, nq4);
        int nk4 = KVh * Dd * HID / 4;
        k_split<<<(nk4 + 255) / 256, 256>>>(kw, wh + Hh * Dd * HID,
                                            wl + Hh * Dd * HID, nk4);
        k_split<<<(nk4 + 255) / 256, 256>>>(vw, wh + (Hh + KVh) * Dd * HID,
                                            wl + (Hh + KVh) * Dd * HID, nk4);
        int no4 = HID * Hh * Dd / 4;
        k_split<<<(no4 + 255) / 256, 256>>>(ow, owh, owl, no4);
    }

    // 2) fused QKV projection: [4096,2048] @ [4096,2048]^T -> [4096,4096]
    {
        dim3 g(NQKV / 64, MROWS / 64, 1);
        k_gemm3<true, true, true><<<g, 128>>>(xh, xl, wh, wl, qkvp,
                                              MROWS, NQKV, HID, NQKV,
                                              0, 0, 0, 0, 0, 0, 1, 1, 0);
    }

    // 3) RMSNorm + RoPE + split, reorganize to [B,(KV)H,S,D]
    k_qkvpost<<<32768, 128>>>(qkvp, pe, qnw, knw, qh, ql, kh, kl, vh, vl);

    // 4) scores = q @ k^T (causal block-skip), [B,H,S,S]
    {
        dim3 g(Ss / 64, Ss / 64, Bz * Hh);
        k_gemm3<true, true, true><<<g, 128>>>(
            qh, ql, kh, kl, sc, Ss, Ss, Dd, Ss,
            (long long)Hh * Ss * Dd, (long long)Ss * Dd,
            (long long)KVh * Ss * Dd, (long long)Ss * Dd,
            (long long)Hh * Ss * Ss, (long long)Ss * Ss,
            Hh, Hh / KVh, 1);
    }

    // 5) causal softmax (in-place, tf32-rounded, zero-fills tile edge)
    k_softmax<<<Bz * Hh * Ss, 128>>>(sc);

    // 6) attnout = attn @ v  (K-trimmed per M tile), write [B,S,H,D]
    {
        dim3 g(Dd / 64, Ss / 64, Bz * Hh);
        k_gemm3<false, true, false><<<g, 128>>>(
            sc, nullptr, vh, vl, ao, Ss, Dd, Ss, Hh * Dd,
            (long long)Hh * Ss * Ss, (long long)Ss * Ss,
            (long long)KVh * Ss * Dd, (long long)Ss * Dd,
            (long long)Ss * Hh * Dd, (long long)Dd,
            Hh, Hh / KVh, 2);
    }

    // 7) split attnout for the final 3xTF32 GEMM
    {
        int n4 = MROWS * Hh * Dd / 4;
        k_split<<<(n4 + 255) / 256, 256>>>(ao, aoh, aol, n4);
    }

    // 8) out = attnout @ o_w^T -> d_out [4096, 2048]
    {
        dim3 g(HID / 64, MROWS / 64, 1);
        k_gemm3<true, true, true><<<g, 128>>>(aoh, aol, owh, owl, out,
                                              MROWS, HID, Hh * Dd, HID,
                                              0, 0, 0, 0, 0, 0, 1, 1, 0);
    }
}

// round 6
// speedup vs baseline: 2.7220x; 2.7220x over previous
#include <cuda_runtime.h>
#include <cuda_bf16.h>
#include <mma.h>
#include <cstdint>

using namespace nvcuda;
typedef __nv_bfloat16 bf16;
typedef __nv_bfloat162 bf162;

// ---------------- problem constants ----------------
constexpr int Bz  = 2;
constexpr int Ss  = 2048;
constexpr int HID = 2048;
constexpr int Hh  = 16;
constexpr int KVh = 8;
constexpr int Dd  = 128;
constexpr int MROWS = Bz * Ss;                 // 4096
constexpr int NQKV  = (Hh + 2 * KVh) * Dd;     // 4096
constexpr float SCALE_Q = 0.08838834764831845f; // 1/sqrt(128)

// ---------------- scratch (static device memory) ----------------
__device__ bf16 g_xh[MROWS * HID], g_xl[MROWS * HID];
__device__ bf16 g_wh[NQKV * HID],  g_wl[NQKV * HID];
__device__ bf16 g_owh[HID * Hh * Dd], g_owl[HID * Hh * Dd];
__device__ float g_qkv[(size_t)MROWS * NQKV];
constexpr size_t QN = (size_t)Bz * Hh * Ss * Dd;
constexpr size_t KN = (size_t)Bz * KVh * Ss * Dd;
__device__ bf16 g_qh[QN], g_ql[QN];
__device__ bf16 g_kh[KN], g_kl[KN];
__device__ bf16 g_vh[KN], g_vl[KN];
__device__ bf16 g_vth[KN], g_vtl[KN];
constexpr size_t SCN = (size_t)Bz * Hh * Ss * Ss;
__device__ float g_sc[SCN];
__device__ bf16 g_ph[SCN], g_pl[SCN];
__device__ bf16 g_aoh[(size_t)MROWS * Hh * Dd], g_aol[(size_t)MROWS * Hh * Dd];

// ---------------- helpers ----------------
__device__ __forceinline__ uint32_t s2u(const void* p) {
    uint32_t a;
    asm("{ .reg .u64 t; cvta.to.shared.u64 t, %1; cvt.u32.u64 %0, t; }" : "=r"(a) : "l"(p));
    return a;
}
__device__ __forceinline__ void cpa16(uint32_t dst, const void* src) {
    asm volatile("cp.async.cg.shared.global [%0], [%1], 16;" :: "r"(dst), "l"(src) : "memory");
}
#define CP_COMMIT() asm volatile("cp.async.commit_group;" ::: "memory")
#define CP_WAIT(n)  asm volatile("cp.async.wait_group %0;" :: "n"(n) : "memory")

__device__ __forceinline__ void wsb(bf16* __restrict__ hi, bf16* __restrict__ lo,
                                    long long i, float v) {
    bf16 h = __float2bfloat16(v);
    hi[i] = h;
    lo[i] = __float2bfloat16(v - __bfloat162float(h));
}

// ---------------- HMMA bf16-split batched GEMM ----------------
// C[m,n] = sum_k A[m,k]*B[n,k], A = Ah+Al, B = Bh+Bl (bf16 hi/lo of fp32).
// Terms: Ah*Bh + Al*Bh + Ah*Bl. CTA tile 128x128, K-chunk 32, cp.async x2 buf.
// EPI 0: fp32 C; EPI 1: bf16 split Chi/Clo.
// causal 0: none; 1: skip n0>m0; 2: Kend = m0+128.
constexpr int LDA   = 56;                     // smem leading dim (elems); 112B rows
constexpr int MATB  = 128 * LDA * 2;          // 14336 B per matrix tile
constexpr int STAGE = 4 * MATB;               // 57344 B
constexpr int SMEM_MM = 2 * STAGE;            // 114688 B

template <int EPI>
__global__ __launch_bounds__(256, 1) void k_mm(
    const bf16* __restrict__ Ah, const bf16* __restrict__ Al,
    const bf16* __restrict__ Bh, const bf16* __restrict__ Bl,
    float* __restrict__ C, bf16* __restrict__ Chi, bf16* __restrict__ Clo,
    int K, int ldc,
    long long aSB, long long aSH, long long bSB, long long bSH,
    long long cSB, long long cSH, int Hdim, int gqa, int causal) {
    const int m0 = blockIdx.y * 128, n0 = blockIdx.x * 128;
    if (causal == 1 && n0 > m0) return;

    extern __shared__ __align__(16) char smem[];
    const uint32_t sb = s2u(smem);
    const int tid = threadIdx.x, wid = tid >> 5;

    const int z = blockIdx.z, b = z / Hdim, h = z - b * Hdim;
    const bf16* pAh = Ah + (long long)b * aSB + (long long)h * aSH;
    const bf16* pAl = Al + (long long)b * aSB + (long long)h * aSH;
    const bf16* pBh = Bh + (long long)b * bSB + (long long)(h / gqa) * bSH;
    const bf16* pBl = Bl + (long long)b * bSB + (long long)(h / gqa) * bSH;
    const long long cOff = (long long)b * cSB + (long long)h * cSH;

    // per-thread load slots: 2 x 16B per matrix per chunk (128 rows x 64B)
    uint32_t sdst[2];
    const char *gAh[2], *gAl[2], *gBh[2], *gBl[2];
#pragma unroll
    for (int i = 0; i < 2; i++) {
        int idx = i * 256 + tid, r = idx >> 2, c8 = (idx & 3) << 3;
        sdst[i] = (uint32_t)(r * (LDA * 2) + c8 * 2);
        gAh[i] = (const char*)(pAh + (long long)(m0 + r) * K + c8);
        gAl[i] = (const char*)(pAl + (long long)(m0 + r) * K + c8);
        gBh[i] = (const char*)(pBh + (long long)(n0 + r) * K + c8);
        gBl[i] = (const char*)(pBl + (long long)(n0 + r) * K + c8);
    }

    const int Kend = (causal == 2) ? (m0 + 128) : K;
    const int nch = Kend >> 5;   // K-chunk = 32

    auto loadChunk = [&](int c, int st) {
        const uint32_t base = sb + st * STAGE;
        const long long kb = (long long)c * 64;  // 32 elems * 2B
#pragma unroll
        for (int i = 0; i < 2; i++) {
            cpa16(base + sdst[i],            gAh[i] + kb);
            cpa16(base + MATB + sdst[i],     gAl[i] + kb);
            cpa16(base + 2 * MATB + sdst[i], gBh[i] + kb);
            cpa16(base + 3 * MATB + sdst[i], gBl[i] + kb);
        }
        CP_COMMIT();
    };

    const int wm = (wid & 3) * 32;   // warp row base within tile
    const int wn = (wid >> 2) * 64;  // warp col base within tile

    wmma::fragment<wmma::accumulator, 16, 16, 16, float> acc[2][4];
#pragma unroll
    for (int i = 0; i < 2; i++)
#pragma unroll
        for (int j = 0; j < 4; j++) wmma::fill_fragment(acc[i][j], 0.0f);

    loadChunk(0, 0);
    for (int c = 0; c < nch; c++) {
        if (c + 1 < nch) { loadChunk(c + 1, (c + 1) & 1); CP_WAIT(1); }
        else             { CP_WAIT(0); }
        __syncthreads();

        const char* st = smem + (c & 1) * STAGE;
        const bf16* sAh = (const bf16*)(st);
        const bf16* sAl = (const bf16*)(st + MATB);
        const bf16* sBh = (const bf16*)(st + 2 * MATB);
        const bf16* sBl = (const bf16*)(st + 3 * MATB);

#pragma unroll
        for (int ks = 0; ks < 32; ks += 16) {
            wmma::fragment<wmma::matrix_a, 16, 16, 16, bf16, wmma::row_major> ah[2], al[2];
            wmma::fragment<wmma::matrix_b, 16, 16, 16, bf16, wmma::col_major> bh[4], bl[4];
#pragma unroll
            for (int i = 0; i < 2; i++) {
                wmma::load_matrix_sync(ah[i], sAh + (wm + 16 * i) * LDA + ks, LDA);
                wmma::load_matrix_sync(al[i], sAl + (wm + 16 * i) * LDA + ks, LDA);
            }
#pragma unroll
            for (int j = 0; j < 4; j++) {
                wmma::load_matrix_sync(bh[j], sBh + (wn + 16 * j) * LDA + ks, LDA);
                wmma::load_matrix_sync(bl[j], sBl + (wn + 16 * j) * LDA + ks, LDA);
            }
#pragma unroll
            for (int i = 0; i < 2; i++)
#pragma unroll
                for (int j = 0; j < 4; j++) {
                    wmma::mma_sync(acc[i][j], al[i], bh[j], acc[i][j]);
                    wmma::mma_sync(acc[i][j], ah[i], bl[j], acc[i][j]);
                    wmma::mma_sync(acc[i][j], ah[i], bh[j], acc[i][j]);
                }
        }
        __syncthreads();
    }

    if constexpr (EPI == 0) {
        float* pc = C + cOff;
#pragma unroll
        for (int i = 0; i < 2; i++)
#pragma unroll
            for (int j = 0; j < 4; j++)
                wmma::store_matrix_sync(
                    pc + (long long)(m0 + wm + 16 * i) * ldc + n0 + wn + 16 * j,
                    acc[i][j], ldc, wmma::mem_row_major);
    } else {
        // stage fp32 result in smem, then split-write bf16 hi/lo
        float* cst = (float*)smem;            // 128 x 132 floats = 67584 B
#pragma unroll
        for (int i = 0; i < 2; i++)
#pragma unroll
            for (int j = 0; j < 4; j++)
                wmma::store_matrix_sync(cst + (wm + 16 * i) * 132 + wn + 16 * j,
                                        acc[i][j], 132, wmma::mem_row_major);
        __syncthreads();
        const int row = tid >> 1, cb = (tid & 1) * 64;
        bf16* ph_ = Chi + cOff + (long long)(m0 + row) * ldc + n0 + cb;
        bf16* pl_ = Clo + cOff + (long long)(m0 + row) * ldc + n0 + cb;
        const float* src = cst + row * 132 + cb;
#pragma unroll
        for (int i = 0; i < 32; i++) {
            float a0 = src[2 * i], a1 = src[2 * i + 1];
            bf16 h0 = __float2bfloat16(a0), h1 = __float2bfloat16(a1);
            bf162 hh; hh.x = h0; hh.y = h1;
            bf162 ll;
            ll.x = __float2bfloat16(a0 - __bfloat162float(h0));
            ll.y = __float2bfloat16(a1 - __bfloat162float(h1));
            reinterpret_cast<bf162*>(ph_)[i] = hh;
            reinterpret_cast<bf162*>(pl_)[i] = ll;
        }
    }
}

// ---------------- fp32 -> bf16 hi/lo split ----------------
__global__ void k_split(const float* __restrict__ src, bf16* __restrict__ hi,
                        bf16* __restrict__ lo, int n4) {
    int i = blockIdx.x * blockDim.x + threadIdx.x;
    if (i >= n4) return;
    float4 v = reinterpret_cast<const float4*>(src)[i];
    bf162 h0, h1, l0, l1;
    h0.x = __float2bfloat16(v.x); l0.x = __float2bfloat16(v.x - __bfloat162float(h0.x));
    h0.y = __float2bfloat16(v.y); l0.y = __float2bfloat16(v.y - __bfloat162float(h0.y));
    h1.x = __float2bfloat16(v.z); l1.x = __float2bfloat16(v.z - __bfloat162float(h1.x));
    h1.y = __float2bfloat16(v.w); l1.y = __float2bfloat16(v.w - __bfloat162float(h1.y));
    reinterpret_cast<bf162*>(hi)[2 * i]     = h0;
    reinterpret_cast<bf162*>(hi)[2 * i + 1] = h1;
    reinterpret_cast<bf162*>(lo)[2 * i]     = l0;
    reinterpret_cast<bf162*>(lo)[2 * i + 1] = l1;
}

// ---------------- QKV post: RMSNorm + RoPE + bf16 split ----------------
__global__ void k_qkvpost(const float* __restrict__ qkv, const float* __restrict__ pe,
                          const float* __restrict__ qnw, const float* __restrict__ knw,
                          bf16* __restrict__ qh, bf16* __restrict__ ql,
                          bf16* __restrict__ kh, bf16* __restrict__ kl,
                          bf16* __restrict__ vh, bf16* __restrict__ vl) {
    const int task = blockIdx.x * 4 + (threadIdx.x >> 5);
    const int lane = threadIdx.x & 31;

    if (task < 65536) {  // Q
        const int bs = task >> 4, h = task & 15;
        const float* src = qkv + (long long)bs * NQKV + h * Dd;
        float x0 = src[lane], x1 = src[lane + 32], x2 = src[lane + 64], x3 = src[lane + 96];
        float ss = x0 * x0 + x1 * x1 + x2 * x2 + x3 * x3;
#pragma unroll
        for (int o = 16; o; o >>= 1) ss += __shfl_xor_sync(0xffffffffu, ss, o);
        float inv = rsqrtf(ss * (1.0f / 128.0f) + 1e-6f);
        float n0 = x0 * inv * qnw[lane],      n1 = x1 * inv * qnw[lane + 32];
        float n2 = x2 * inv * qnw[lane + 64], n3 = x3 * inv * qnw[lane + 96];
        const float* per = pe + (long long)bs * Dd;
        float c0 = per[lane],      s0 = per[64 + lane];
        float c1 = per[32 + lane], s1 = per[96 + lane];
        float o0 = (n0 * c0 - n2 * s0) * SCALE_Q;
        float o1 = (n1 * c1 - n3 * s1) * SCALE_Q;
        float o2 = (n0 * s0 + n2 * c0) * SCALE_Q;
        float o3 = (n1 * s1 + n3 * c1) * SCALE_Q;
        const int b = bs >> 11, s = bs & 2047;
        long long base = ((long long)(b * Hh + h) * Ss + s) * Dd;
        wsb(qh, ql, base + lane, o0);       wsb(qh, ql, base + lane + 32, o1);
        wsb(qh, ql, base + lane + 64, o2);  wsb(qh, ql, base + lane + 96, o3);
    } else if (task < 98304) {  // K
        const int t = task - 65536;
        const int bs = t >> 3, kvh = t & 7;
        const float* src = qkv + (long long)bs * NQKV + Hh * Dd + kvh * Dd;
        float x0 = src[lane], x1 = src[lane + 32], x2 = src[lane + 64], x3 = src[lane + 96];
        float ss = x0 * x0 + x1 * x1 + x2 * x2 + x3 * x3;
#pragma unroll
        for (int o = 16; o; o >>= 1) ss += __shfl_xor_sync(0xffffffffu, ss, o);
        float inv = rsqrtf(ss * (1.0f / 128.0f) + 1e-6f);
        float n0 = x0 * inv * knw[lane],      n1 = x1 * inv * knw[lane + 32];
        float n2 = x2 * inv * knw[lane + 64], n3 = x3 * inv * knw[lane + 96];
        const float* per = pe + (long long)bs * Dd;
        float c0 = per[lane],      s0 = per[64 + lane];
        float c1 = per[32 + lane], s1 = per[96 + lane];
        float o0 = n0 * c0 - n2 * s0, o1 = n1 * c1 - n3 * s1;
        float o2 = n0 * s0 + n2 * c0, o3 = n1 * s1 + n3 * c1;
        const int b = bs >> 11, s = bs & 2047;
        long long base = ((long long)(b * KVh + kvh) * Ss + s) * Dd;
        wsb(kh, kl, base + lane, o0);       wsb(kh, kl, base + lane + 32, o1);
        wsb(kh, kl, base + lane + 64, o2);  wsb(kh, kl, base + lane + 96, o3);
    } else {  // V
        const int t = task - 98304;
        const int bs = t >> 3, kvh = t & 7;
        const float* src = qkv + (long long)bs * NQKV + (Hh + KVh) * Dd + kvh * Dd;
        const int b = bs >> 11, s = bs & 2047;
        long long base = ((long long)(b * KVh + kvh) * Ss + s) * Dd;
        wsb(vh, vl, base + lane,      src[lane]);
        wsb(vh, vl, base + lane + 32, src[lane + 32]);
        wsb(vh, vl, base + lane + 64, src[lane + 64]);
        wsb(vh, vl, base + lane + 96, src[lane + 96]);
    }
}

// ---------------- V transpose: [B,KV,S,D] -> [B,KV,D,S] (hi+lo) ----------------
__global__ void k_vt(const bf16* __restrict__ vh, const bf16* __restrict__ vl,
                     bf16* __restrict__ vth, bf16* __restrict__ vtl) {
    __shared__ bf16 th[32][33], tl[32][33];
    const int bz = blockIdx.z;
    const long long base = (long long)bz * Ss * Dd;
    const int s0 = blockIdx.x * 32, d0 = blockIdx.y * 32;
    const int tx = threadIdx.x, ty = threadIdx.y;
#pragma unroll
    for (int j = 0; j < 4; j++) {
        int r = ty + j * 8;
        th[r][tx] = vh[base + (long long)(s0 + r) * Dd + d0 + tx];
        tl[r][tx] = vl[base + (long long)(s0 + r) * Dd + d0 + tx];
    }
    __syncthreads();
#pragma unroll
    for (int j = 0; j < 4; j++) {
        int r = ty + j * 8;
        vth[base + (long long)(d0 + r) * Ss + s0 + tx] = th[tx][r];
        vtl[base + (long long)(d0 + r) * Ss + s0 + tx] = tl[tx][r];
    }
}

// ---------------- causal softmax: fp32 in -> bf16 hi/lo P, zero-padded ----------
__global__ void k_softmax(const float* __restrict__ sc, bf16* __restrict__ ph,
                          bf16* __restrict__ pl) {
    const int row = blockIdx.x;           // [0, B*H*S)
    const int s = row & (Ss - 1);
    const float* p = sc + (long long)row * Ss;
    bf16* oh = ph + (long long)row * Ss;
    bf16* ol = pl + (long long)row * Ss;
    const int L = s + 1;
    const int tid = threadIdx.x;

    float ev[16];
    float mx = -3.4e38f;
    int cnt = 0;
    for (int i = tid; i < L; i += 128) {
        float v = p[i];
        ev[cnt++] = v;
        mx = fmaxf(mx, v);
    }
#pragma unroll
    for (int o = 16; o; o >>= 1) mx = fmaxf(mx, __shfl_xor_sync(0xffffffffu, mx, o));
    __shared__ float shm[4], shs[4];
    if ((tid & 31) == 0) shm[tid >> 5] = mx;
    __syncthreads();
    mx = fmaxf(fmaxf(shm[0], shm[1]), fmaxf(shm[2], shm[3]));

    float sum = 0.0f;
    for (int j = 0; j < cnt; j++) {
        float e = __expf(ev[j] - mx);
        ev[j] = e;
        sum += e;
    }
#pragma unroll
    for (int o = 16; o; o >>= 1) sum += __shfl_xor_sync(0xffffffffu, sum, o);
    if ((tid & 31) == 0) shs[tid >> 5] = sum;
    __syncthreads();
    sum = shs[0] + shs[1] + shs[2] + shs[3];
    const float inv = 1.0f / sum;

    cnt = 0;
    for (int i = tid; i < L; i += 128) {
        float v = ev[cnt++] * inv;
        bf16 h = __float2bfloat16(v);
        oh[i] = h;
        ol[i] = __float2bfloat16(v - __bfloat162float(h));
    }
    const int tileEnd = ((s >> 7) << 7) + 128;  // pad to 128-tile boundary for AV
    bf16 z = __float2bfloat16(0.0f);
    for (int i = L + tid; i < tileEnd; i += 128) { oh[i] = z; ol[i] = z; }
}

// ---------------- launch -----------------------------------------------------
extern "C" void kernel_launch(void* const* d_in, const int* in_sizes, int n_in,
                              void* d_out, int out_size) {
    (void)in_sizes; (void)n_in; (void)out_size;
    const float* x   = (const float*)d_in[0];
    const float* pe  = (const float*)d_in[1];
    const float* qw  = (const float*)d_in[2];
    const float* kw  = (const float*)d_in[3];
    const float* vw  = (const float*)d_in[4];
    const float* ow  = (const float*)d_in[5];
    const float* qnw = (const float*)d_in[6];
    const float* knw = (const float*)d_in[7];
    float* out = (float*)d_out;

    bf16 *xh, *xl, *wh, *wl, *owh, *owl;
    bf16 *qh, *ql, *kh, *kl, *vh, *vl, *vth, *vtl, *ph, *pl, *aoh, *aol;
    float *qkvp, *sc;
    cudaGetSymbolAddress((void**)&xh, g_xh);   cudaGetSymbolAddress((void**)&xl, g_xl);
    cudaGetSymbolAddress((void**)&wh, g_wh);   cudaGetSymbolAddress((void**)&wl, g_wl);
    cudaGetSymbolAddress((void**)&owh, g_owh); cudaGetSymbolAddress((void**)&owl, g_owl);
    cudaGetSymbolAddress((void**)&qkvp, g_qkv);
    cudaGetSymbolAddress((void**)&qh, g_qh);   cudaGetSymbolAddress((void**)&ql, g_ql);
    cudaGetSymbolAddress((void**)&kh, g_kh);   cudaGetSymbolAddress((void**)&kl, g_kl);
    cudaGetSymbolAddress((void**)&vh, g_vh);   cudaGetSymbolAddress((void**)&vl, g_vl);
    cudaGetSymbolAddress((void**)&vth, g_vth); cudaGetSymbolAddress((void**)&vtl, g_vtl);
    cudaGetSymbolAddress((void**)&sc, g_sc);
    cudaGetSymbolAddress((void**)&ph, g_ph);   cudaGetSymbolAddress((void**)&pl, g_pl);
    cudaGetSymbolAddress((void**)&aoh, g_aoh); cudaGetSymbolAddress((void**)&aol, g_aol);

    cudaFuncSetAttribute(k_mm<0>, cudaFuncAttributeMaxDynamicSharedMemorySize, SMEM_MM);
    cudaFuncSetAttribute(k_mm<1>, cudaFuncAttributeMaxDynamicSharedMemorySize, SMEM_MM);

    // 1) bf16 splits of x and weights
    {
        int n4 = MROWS * HID / 4;
        k_split<<<(n4 + 255) / 256, 256>>>(x, xh, xl, n4);
        int nq4 = Hh * Dd * HID / 4;
        k_split<<<(nq4 + 255) / 256, 256>>>(qw, wh, wl, nq4);
        int nk4 = KVh * Dd * HID / 4;
        k_split<<<(nk4 + 255) / 256, 256>>>(kw, wh + Hh * Dd * HID,
                                            wl + Hh * Dd * HID, nk4);
        k_split<<<(nk4 + 255) / 256, 256>>>(vw, wh + (Hh + KVh) * Dd * HID,
                                            wl + (Hh + KVh) * Dd * HID, nk4);
        int no4 = HID * Hh * Dd / 4;
        k_split<<<(no4 + 255) / 256, 256>>>(ow, owh, owl, no4);
    }

    // 2) QKV projection: [4096,2048] @ [4096,2048]^T -> g_qkv [4096,4096] fp32
    {
        dim3 g(NQKV / 128, MROWS / 128, 1);
        k_mm<0><<<g, 256, SMEM_MM>>>(xh, xl, wh, wl, qkvp, nullptr, nullptr,
                                     HID, NQKV, 0, 0, 0, 0, 0, 0, 1, 1, 0);
    }

    // 3) RMSNorm + RoPE + bf16 split -> q/k/v [B,(KV)H,S,D]
    k_qkvpost<<<32768, 128>>>(qkvp, pe, qnw, knw, qh, ql, kh, kl, vh, vl);

    // 4) V transpose -> [B,KV,D,S]
    {
        dim3 g(Ss / 32, Dd / 32, Bz * KVh);
        k_vt<<<g, dim3(32, 8)>>>(vh, vl, vth, vtl);
    }

    // 5) scores = q @ k^T (causal tile-skip) -> g_sc fp32 [B,H,S,S]
    {
        dim3 g(Ss / 128, Ss / 128, Bz * Hh);
        k_mm<0><<<g, 256, SMEM_MM>>>(
            qh, ql, kh, kl, sc, nullptr, nullptr, Dd, Ss,
            (long long)Hh * Ss * Dd, (long long)Ss * Dd,
            (long long)KVh * Ss * Dd, (long long)Ss * Dd,
            (long long)Hh * Ss * Ss, (long long)Ss * Ss,
            Hh, Hh / KVh, 1);
    }

    // 6) softmax -> P bf16 hi/lo, zero-padded to tile edge
    k_softmax<<<Bz * Hh * Ss, 128>>>(sc, ph, pl);

    // 7) attnout = P @ V^T (K-trimmed), epilogue writes bf16 hi/lo [B,S,H,D]
    {
        dim3 g(1, Ss / 128, Bz * Hh);
        k_mm<1><<<g, 256, SMEM_MM>>>(
            ph, pl, vth, vtl, nullptr, aoh, aol, Ss, Hh * Dd,
            (long long)Hh * Ss * Ss, (long long)Ss * Ss,
            (long long)KVh * Dd * Ss, (long long)Dd * Ss,
            (long long)Ss * Hh * Dd, (long long)Dd,
            Hh, Hh / KVh, 2);
    }

    // 8) out = attnout @ o_w^T -> d_out [4096,2048] fp32
    {
        dim3 g(HID / 128, MROWS / 128, 1);
        k_mm<0><<<g, 256, SMEM_MM>>>(aoh, aol, owh, owl, out, nullptr, nullptr,
                                     Hh * Dd, HID, 0, 0, 0, 0, 0, 0, 1, 1, 0);
    }
}

// round 7
// speedup vs baseline: 3.1966x; 1.1743x over previous
#include <cuda_runtime.h>
#include <cuda_bf16.h>
#include <mma.h>
#include <cstdint>

using namespace nvcuda;
typedef __nv_bfloat16 bf16;
typedef __nv_bfloat162 bf162;

// ---------------- problem constants ----------------
constexpr int Bz  = 2;
constexpr int Ss  = 2048;
constexpr int HID = 2048;
constexpr int Hh  = 16;
constexpr int KVh = 8;
constexpr int Dd  = 128;
constexpr int MROWS = Bz * Ss;                 // 4096
constexpr int NQKV  = (Hh + 2 * KVh) * Dd;     // 4096
constexpr float SCALE_Q = 0.08838834764831845f; // 1/sqrt(128)

// ---------------- scratch (static device memory) ----------------
__device__ bf16 g_xh[MROWS * HID], g_xl[MROWS * HID];
__device__ bf16 g_wh[NQKV * HID],  g_wl[NQKV * HID];
__device__ bf16 g_owh[HID * Hh * Dd], g_owl[HID * Hh * Dd];
__device__ float g_qkv[(size_t)MROWS * NQKV];
constexpr size_t QN = (size_t)Bz * Hh * Ss * Dd;
constexpr size_t KN = (size_t)Bz * KVh * Ss * Dd;
__device__ bf16 g_qh[QN], g_ql[QN];
__device__ bf16 g_kh[KN], g_kl[KN];
__device__ bf16 g_vh[KN], g_vl[KN];
__device__ bf16 g_vth[KN], g_vtl[KN];
constexpr size_t SCN = (size_t)Bz * Hh * Ss * Ss;
__device__ float g_sc[SCN];
__device__ bf16 g_ph[SCN], g_pl[SCN];
__device__ bf16 g_aoh[(size_t)MROWS * Hh * Dd], g_aol[(size_t)MROWS * Hh * Dd];

// ---------------- helpers ----------------
__device__ __forceinline__ uint32_t s2u(const void* p) {
    uint32_t a;
    asm("{ .reg .u64 t; cvta.to.shared.u64 t, %1; cvt.u32.u64 %0, t; }" : "=r"(a) : "l"(p));
    return a;
}
__device__ __forceinline__ void cpa16(uint32_t dst, const void* src) {
    asm volatile("cp.async.cg.shared.global [%0], [%1], 16;" :: "r"(dst), "l"(src) : "memory");
}
#define CP_COMMIT() asm volatile("cp.async.commit_group;" ::: "memory")
#define CP_WAIT(n)  asm volatile("cp.async.wait_group %0;" :: "n"(n) : "memory")

__device__ __forceinline__ void wsb(bf16* __restrict__ hi, bf16* __restrict__ lo,
                                    long long i, float v) {
    bf16 h = __float2bfloat16(v);
    hi[i] = h;
    lo[i] = __float2bfloat16(v - __bfloat162float(h));
}

// ---------------- HMMA bf16-split batched GEMM ----------------
// C[m,n] = sum_k A[m,k]*B[n,k], A = Ah+Al, B = Bh+Bl (bf16 hi/lo of fp32).
// Terms: Ah*Bh + Al*Bh + Ah*Bl. CTA tile 128x128, K-chunk 32, cp.async x2 buf.
// LDA=40 (80B pitch): ldmatrix phase pattern (5r+j) mod 8 -> conflict-free.
// 2 CTAs/SM (80KB smem, <=128 regs) to overlap barrier/memory stalls.
// EPI 0: fp32 C; EPI 1: bf16 split Chi/Clo.
// causal 0: none; 1: skip n0>m0; 2: Kend = m0+128.
constexpr int LDA   = 40;                     // smem leading dim (elems); 80B rows
constexpr int MATB  = 128 * LDA * 2;          // 10240 B per matrix tile
constexpr int STAGE = 4 * MATB;               // 40960 B
constexpr int SMEM_MM = 2 * STAGE;            // 81920 B

template <int EPI>
__global__ __launch_bounds__(256, 2) void k_mm(
    const bf16* __restrict__ Ah, const bf16* __restrict__ Al,
    const bf16* __restrict__ Bh, const bf16* __restrict__ Bl,
    float* __restrict__ C, bf16* __restrict__ Chi, bf16* __restrict__ Clo,
    int K, int ldc,
    long long aSB, long long aSH, long long bSB, long long bSH,
    long long cSB, long long cSH, int Hdim, int gqa, int causal) {
    const int m0 = blockIdx.y * 128, n0 = blockIdx.x * 128;
    if (causal == 1 && n0 > m0) return;

    extern __shared__ __align__(16) char smem[];
    const uint32_t sb = s2u(smem);
    const int tid = threadIdx.x, wid = tid >> 5;

    const int z = blockIdx.z, b = z / Hdim, h = z - b * Hdim;
    const bf16* pAh = Ah + (long long)b * aSB + (long long)h * aSH;
    const bf16* pAl = Al + (long long)b * aSB + (long long)h * aSH;
    const bf16* pBh = Bh + (long long)b * bSB + (long long)(h / gqa) * bSH;
    const bf16* pBl = Bl + (long long)b * bSB + (long long)(h / gqa) * bSH;
    const long long cOff = (long long)b * cSB + (long long)h * cSH;

    // per-thread load slots: 2 x 16B per matrix per chunk (128 rows x 64B)
    uint32_t sdst[2];
    long long offA[2];
    const long long dBA = (long long)(n0 - m0) * K;   // offB = offA + dBA
#pragma unroll
    for (int i = 0; i < 2; i++) {
        int idx = i * 256 + tid, r = idx >> 2, c8 = (idx & 3) << 3;
        sdst[i] = (uint32_t)(r * (LDA * 2) + c8 * 2);
        offA[i] = (long long)(m0 + r) * K + c8;
    }

    const int Kend = (causal == 2) ? (m0 + 128) : K;
    const int nch = Kend >> 5;   // K-chunk = 32

    auto loadChunk = [&](int c, int st) {
        const uint32_t base = sb + st * STAGE;
        const long long kb = (long long)c * 32;   // elements
#pragma unroll
        for (int i = 0; i < 2; i++) {
            const long long oa = offA[i] + kb, ob = oa + dBA;
            cpa16(base + sdst[i],            pAh + oa);
            cpa16(base + MATB + sdst[i],     pAl + oa);
            cpa16(base + 2 * MATB + sdst[i], pBh + ob);
            cpa16(base + 3 * MATB + sdst[i], pBl + ob);
        }
        CP_COMMIT();
    };

    const int wm = (wid & 3) * 32;   // warp row base within tile
    const int wn = (wid >> 2) * 64;  // warp col base within tile

    wmma::fragment<wmma::accumulator, 16, 16, 16, float> acc[2][4];
#pragma unroll
    for (int i = 0; i < 2; i++)
#pragma unroll
        for (int j = 0; j < 4; j++) wmma::fill_fragment(acc[i][j], 0.0f);

    loadChunk(0, 0);
    for (int c = 0; c < nch; c++) {
        if (c + 1 < nch) { loadChunk(c + 1, (c + 1) & 1); CP_WAIT(1); }
        else             { CP_WAIT(0); }
        __syncthreads();

        const char* st = smem + (c & 1) * STAGE;
        const bf16* sAh = (const bf16*)(st);
        const bf16* sAl = (const bf16*)(st + MATB);
        const bf16* sBh = (const bf16*)(st + 2 * MATB);
        const bf16* sBl = (const bf16*)(st + 3 * MATB);

#pragma unroll
        for (int ks = 0; ks < 32; ks += 16) {
            wmma::fragment<wmma::matrix_a, 16, 16, 16, bf16, wmma::row_major> ah[2], al[2];
#pragma unroll
            for (int i = 0; i < 2; i++) {
                wmma::load_matrix_sync(ah[i], sAh + (wm + 16 * i) * LDA + ks, LDA);
                wmma::load_matrix_sync(al[i], sAl + (wm + 16 * i) * LDA + ks, LDA);
            }
#pragma unroll
            for (int j = 0; j < 4; j++) {
                wmma::fragment<wmma::matrix_b, 16, 16, 16, bf16, wmma::col_major> bh, bl;
                wmma::load_matrix_sync(bh, sBh + (wn + 16 * j) * LDA + ks, LDA);
                wmma::load_matrix_sync(bl, sBl + (wn + 16 * j) * LDA + ks, LDA);
#pragma unroll
                for (int i = 0; i < 2; i++) {
                    wmma::mma_sync(acc[i][j], al[i], bh, acc[i][j]);
                    wmma::mma_sync(acc[i][j], ah[i], bl, acc[i][j]);
                    wmma::mma_sync(acc[i][j], ah[i], bh, acc[i][j]);
                }
            }
        }
        __syncthreads();
    }

    if constexpr (EPI == 0) {
        float* pc = C + cOff;
#pragma unroll
        for (int i = 0; i < 2; i++)
#pragma unroll
            for (int j = 0; j < 4; j++)
                wmma::store_matrix_sync(
                    pc + (long long)(m0 + wm + 16 * i) * ldc + n0 + wn + 16 * j,
                    acc[i][j], ldc, wmma::mem_row_major);
    } else {
        // stage fp32 result in smem, then split-write bf16 hi/lo
        float* cst = (float*)smem;            // 128 x 132 floats = 67584 B <= 81920
#pragma unroll
        for (int i = 0; i < 2; i++)
#pragma unroll
            for (int j = 0; j < 4; j++)
                wmma::store_matrix_sync(cst + (wm + 16 * i) * 132 + wn + 16 * j,
                                        acc[i][j], 132, wmma::mem_row_major);
        __syncthreads();
        const int row = tid >> 1, cb = (tid & 1) * 64;
        bf16* ph_ = Chi + cOff + (long long)(m0 + row) * ldc + n0 + cb;
        bf16* pl_ = Clo + cOff + (long long)(m0 + row) * ldc + n0 + cb;
        const float* src = cst + row * 132 + cb;
#pragma unroll
        for (int i = 0; i < 32; i++) {
            float a0 = src[2 * i], a1 = src[2 * i + 1];
            bf16 h0 = __float2bfloat16(a0), h1 = __float2bfloat16(a1);
            bf162 hh; hh.x = h0; hh.y = h1;
            bf162 ll;
            ll.x = __float2bfloat16(a0 - __bfloat162float(h0));
            ll.y = __float2bfloat16(a1 - __bfloat162float(h1));
            reinterpret_cast<bf162*>(ph_)[i] = hh;
            reinterpret_cast<bf162*>(pl_)[i] = ll;
        }
    }
}

// ---------------- fp32 -> bf16 hi/lo split ----------------
__global__ void k_split(const float* __restrict__ src, bf16* __restrict__ hi,
                        bf16* __restrict__ lo, int n4) {
    int i = blockIdx.x * blockDim.x + threadIdx.x;
    if (i >= n4) return;
    float4 v = reinterpret_cast<const float4*>(src)[i];
    bf162 h0, h1, l0, l1;
    h0.x = __float2bfloat16(v.x); l0.x = __float2bfloat16(v.x - __bfloat162float(h0.x));
    h0.y = __float2bfloat16(v.y); l0.y = __float2bfloat16(v.y - __bfloat162float(h0.y));
    h1.x = __float2bfloat16(v.z); l1.x = __float2bfloat16(v.z - __bfloat162float(h1.x));
    h1.y = __float2bfloat16(v.w); l1.y = __float2bfloat16(v.w - __bfloat162float(h1.y));
    reinterpret_cast<bf162*>(hi)[2 * i]     = h0;
    reinterpret_cast<bf162*>(hi)[2 * i + 1] = h1;
    reinterpret_cast<bf162*>(lo)[2 * i]     = l0;
    reinterpret_cast<bf162*>(lo)[2 * i + 1] = l1;
}

// ---------------- QKV post: RMSNorm + RoPE + bf16 split ----------------
__global__ void k_qkvpost(const float* __restrict__ qkv, const float* __restrict__ pe,
                          const float* __restrict__ qnw, const float* __restrict__ knw,
                          bf16* __restrict__ qh, bf16* __restrict__ ql,
                          bf16* __restrict__ kh, bf16* __restrict__ kl,
                          bf16* __restrict__ vh, bf16* __restrict__ vl) {
    const int task = blockIdx.x * 4 + (threadIdx.x >> 5);
    const int lane = threadIdx.x & 31;

    if (task < 65536) {  // Q
        const int bs = task >> 4, h = task & 15;
        const float* src = qkv + (long long)bs * NQKV + h * Dd;
        float x0 = src[lane], x1 = src[lane + 32], x2 = src[lane + 64], x3 = src[lane + 96];
        float ss = x0 * x0 + x1 * x1 + x2 * x2 + x3 * x3;
#pragma unroll
        for (int o = 16; o; o >>= 1) ss += __shfl_xor_sync(0xffffffffu, ss, o);
        float inv = rsqrtf(ss * (1.0f / 128.0f) + 1e-6f);
        float n0 = x0 * inv * qnw[lane],      n1 = x1 * inv * qnw[lane + 32];
        float n2 = x2 * inv * qnw[lane + 64], n3 = x3 * inv * qnw[lane + 96];
        const float* per = pe + (long long)bs * Dd;
        float c0 = per[lane],      s0 = per[64 + lane];
        float c1 = per[32 + lane], s1 = per[96 + lane];
        float o0 = (n0 * c0 - n2 * s0) * SCALE_Q;
        float o1 = (n1 * c1 - n3 * s1) * SCALE_Q;
        float o2 = (n0 * s0 + n2 * c0) * SCALE_Q;
        float o3 = (n1 * s1 + n3 * c1) * SCALE_Q;
        const int b = bs >> 11, s = bs & 2047;
        long long base = ((long long)(b * Hh + h) * Ss + s) * Dd;
        wsb(qh, ql, base + lane, o0);       wsb(qh, ql, base + lane + 32, o1);
        wsb(qh, ql, base + lane + 64, o2);  wsb(qh, ql, base + lane + 96, o3);
    } else if (task < 98304) {  // K
        const int t = task - 65536;
        const int bs = t >> 3, kvh = t & 7;
        const float* src = qkv + (long long)bs * NQKV + Hh * Dd + kvh * Dd;
        float x0 = src[lane], x1 = src[lane + 32], x2 = src[lane + 64], x3 = src[lane + 96];
        float ss = x0 * x0 + x1 * x1 + x2 * x2 + x3 * x3;
#pragma unroll
        for (int o = 16; o; o >>= 1) ss += __shfl_xor_sync(0xffffffffu, ss, o);
        float inv = rsqrtf(ss * (1.0f / 128.0f) + 1e-6f);
        float n0 = x0 * inv * knw[lane],      n1 = x1 * inv * knw[lane + 32];
        float n2 = x2 * inv * knw[lane + 64], n3 = x3 * inv * knw[lane + 96];
        const float* per = pe + (long long)bs * Dd;
        float c0 = per[lane],      s0 = per[64 + lane];
        float c1 = per[32 + lane], s1 = per[96 + lane];
        float o0 = n0 * c0 - n2 * s0, o1 = n1 * c1 - n3 * s1;
        float o2 = n0 * s0 + n2 * c0, o3 = n1 * s1 + n3 * c1;
        const int b = bs >> 11, s = bs & 2047;
        long long base = ((long long)(b * KVh + kvh) * Ss + s) * Dd;
        wsb(kh, kl, base + lane, o0);       wsb(kh, kl, base + lane + 32, o1);
        wsb(kh, kl, base + lane + 64, o2);  wsb(kh, kl, base + lane + 96, o3);
    } else {  // V
        const int t = task - 98304;
        const int bs = t >> 3, kvh = t & 7;
        const float* src = qkv + (long long)bs * NQKV + (Hh + KVh) * Dd + kvh * Dd;
        const int b = bs >> 11, s = bs & 2047;
        long long base = ((long long)(b * KVh + kvh) * Ss + s) * Dd;
        wsb(vh, vl, base + lane,      src[lane]);
        wsb(vh, vl, base + lane + 32, src[lane + 32]);
        wsb(vh, vl, base + lane + 64, src[lane + 64]);
        wsb(vh, vl, base + lane + 96, src[lane + 96]);
    }
}

// ---------------- V transpose: [B,KV,S,D] -> [B,KV,D,S] (hi+lo) ----------------
__global__ void k_vt(const bf16* __restrict__ vh, const bf16* __restrict__ vl,
                     bf16* __restrict__ vth, bf16* __restrict__ vtl) {
    __shared__ bf16 th[32][33], tl[32][33];
    const int bz = blockIdx.z;
    const long long base = (long long)bz * Ss * Dd;
    const int s0 = blockIdx.x * 32, d0 = blockIdx.y * 32;
    const int tx = threadIdx.x, ty = threadIdx.y;
#pragma unroll
    for (int j = 0; j < 4; j++) {
        int r = ty + j * 8;
        th[r][tx] = vh[base + (long long)(s0 + r) * Dd + d0 + tx];
        tl[r][tx] = vl[base + (long long)(s0 + r) * Dd + d0 + tx];
    }
    __syncthreads();
#pragma unroll
    for (int j = 0; j < 4; j++) {
        int r = ty + j * 8;
        vth[base + (long long)(d0 + r) * Ss + s0 + tx] = th[tx][r];
        vtl[base + (long long)(d0 + r) * Ss + s0 + tx] = tl[tx][r];
    }
}

// ---------------- causal softmax: fp32 in -> bf16 hi/lo P, zero-padded ----------
__global__ void k_softmax(const float* __restrict__ sc, bf16* __restrict__ ph,
                          bf16* __restrict__ pl) {
    const int row = blockIdx.x;           // [0, B*H*S)
    const int s = row & (Ss - 1);
    const float* p = sc + (long long)row * Ss;
    bf16* oh = ph + (long long)row * Ss;
    bf16* ol = pl + (long long)row * Ss;
    const int L = s + 1;
    const int tid = threadIdx.x;

    float ev[16];
    float mx = -3.4e38f;
    int cnt = 0;
    for (int i = tid; i < L; i += 128) {
        float v = p[i];
        ev[cnt++] = v;
        mx = fmaxf(mx, v);
    }
#pragma unroll
    for (int o = 16; o; o >>= 1) mx = fmaxf(mx, __shfl_xor_sync(0xffffffffu, mx, o));
    __shared__ float shm[4], shs[4];
    if ((tid & 31) == 0) shm[tid >> 5] = mx;
    __syncthreads();
    mx = fmaxf(fmaxf(shm[0], shm[1]), fmaxf(shm[2], shm[3]));

    float sum = 0.0f;
    for (int j = 0; j < cnt; j++) {
        float e = __expf(ev[j] - mx);
        ev[j] = e;
        sum += e;
    }
#pragma unroll
    for (int o = 16; o; o >>= 1) sum += __shfl_xor_sync(0xffffffffu, sum, o);
    if ((tid & 31) == 0) shs[tid >> 5] = sum;
    __syncthreads();
    sum = shs[0] + shs[1] + shs[2] + shs[3];
    const float inv = 1.0f / sum;

    cnt = 0;
    for (int i = tid; i < L; i += 128) {
        float v = ev[cnt++] * inv;
        bf16 h = __float2bfloat16(v);
        oh[i] = h;
        ol[i] = __float2bfloat16(v - __bfloat162float(h));
    }
    const int tileEnd = ((s >> 7) << 7) + 128;  // pad to 128-tile boundary for AV
    bf16 z = __float2bfloat16(0.0f);
    for (int i = L + tid; i < tileEnd; i += 128) { oh[i] = z; ol[i] = z; }
}

// ---------------- launch -----------------------------------------------------
extern "C" void kernel_launch(void* const* d_in, const int* in_sizes, int n_in,
                              void* d_out, int out_size) {
    (void)in_sizes; (void)n_in; (void)out_size;
    const float* x   = (const float*)d_in[0];
    const float* pe  = (const float*)d_in[1];
    const float* qw  = (const float*)d_in[2];
    const float* kw  = (const float*)d_in[3];
    const float* vw  = (const float*)d_in[4];
    const float* ow  = (const float*)d_in[5];
    const float* qnw = (const float*)d_in[6];
    const float* knw = (const float*)d_in[7];
    float* out = (float*)d_out;

    bf16 *xh, *xl, *wh, *wl, *owh, *owl;
    bf16 *qh, *ql, *kh, *kl, *vh, *vl, *vth, *vtl, *ph, *pl, *aoh, *aol;
    float *qkvp, *sc;
    cudaGetSymbolAddress((void**)&xh, g_xh);   cudaGetSymbolAddress((void**)&xl, g_xl);
    cudaGetSymbolAddress((void**)&wh, g_wh);   cudaGetSymbolAddress((void**)&wl, g_wl);
    cudaGetSymbolAddress((void**)&owh, g_owh); cudaGetSymbolAddress((void**)&owl, g_owl);
    cudaGetSymbolAddress((void**)&qkvp, g_qkv);
    cudaGetSymbolAddress((void**)&qh, g_qh);   cudaGetSymbolAddress((void**)&ql, g_ql);
    cudaGetSymbolAddress((void**)&kh, g_kh);   cudaGetSymbolAddress((void**)&kl, g_kl);
    cudaGetSymbolAddress((void**)&vh, g_vh);   cudaGetSymbolAddress((void**)&vl, g_vl);
    cudaGetSymbolAddress((void**)&vth, g_vth); cudaGetSymbolAddress((void**)&vtl, g_vtl);
    cudaGetSymbolAddress((void**)&sc, g_sc);
    cudaGetSymbolAddress((void**)&ph, g_ph);   cudaGetSymbolAddress((void**)&pl, g_pl);
    cudaGetSymbolAddress((void**)&aoh, g_aoh); cudaGetSymbolAddress((void**)&aol, g_aol);

    cudaFuncSetAttribute(k_mm<0>, cudaFuncAttributeMaxDynamicSharedMemorySize, SMEM_MM);
    cudaFuncSetAttribute(k_mm<1>, cudaFuncAttributeMaxDynamicSharedMemorySize, SMEM_MM);

    // 1) bf16 splits of x and weights
    {
        int n4 = MROWS * HID / 4;
        k_split<<<(n4 + 255) / 256, 256>>>(x, xh, xl, n4);
        int nq4 = Hh * Dd * HID / 4;
        k_split<<<(nq4 + 255) / 256, 256>>>(qw, wh, wl, nq4);
        int nk4 = KVh * Dd * HID / 4;
        k_split<<<(nk4 + 255) / 256, 256>>>(kw, wh + Hh * Dd * HID,
                                            wl + Hh * Dd * HID, nk4);
        k_split<<<(nk4 + 255) / 256, 256>>>(vw, wh + (Hh + KVh) * Dd * HID,
                                            wl + (Hh + KVh) * Dd * HID, nk4);
        int no4 = HID * Hh * Dd / 4;
        k_split<<<(no4 + 255) / 256, 256>>>(ow, owh, owl, no4);
    }

    // 2) QKV projection: [4096,2048] @ [4096,2048]^T -> g_qkv [4096,4096] fp32
    {
        dim3 g(NQKV / 128, MROWS / 128, 1);
        k_mm<0><<<g, 256, SMEM_MM>>>(xh, xl, wh, wl, qkvp, nullptr, nullptr,
                                     HID, NQKV, 0, 0, 0, 0, 0, 0, 1, 1, 0);
    }

    // 3) RMSNorm + RoPE + bf16 split -> q/k/v [B,(KV)H,S,D]
    k_qkvpost<<<32768, 128>>>(qkvp, pe, qnw, knw, qh, ql, kh, kl, vh, vl);

    // 4) V transpose -> [B,KV,D,S]
    {
        dim3 g(Ss / 32, Dd / 32, Bz * KVh);
        k_vt<<<g, dim3(32, 8)>>>(vh, vl, vth, vtl);
    }

    // 5) scores = q @ k^T (causal tile-skip) -> g_sc fp32 [B,H,S,S]
    {
        dim3 g(Ss / 128, Ss / 128, Bz * Hh);
        k_mm<0><<<g, 256, SMEM_MM>>>(
            qh, ql, kh, kl, sc, nullptr, nullptr, Dd, Ss,
            (long long)Hh * Ss * Dd, (long long)Ss * Dd,
            (long long)KVh * Ss * Dd, (long long)Ss * Dd,
            (long long)Hh * Ss * Ss, (long long)Ss * Ss,
            Hh, Hh / KVh, 1);
    }

    // 6) softmax -> P bf16 hi/lo, zero-padded to tile edge
    k_softmax<<<Bz * Hh * Ss, 128>>>(sc, ph, pl);

    // 7) attnout = P @ V^T (K-trimmed), epilogue writes bf16 hi/lo [B,S,H,D]
    {
        dim3 g(1, Ss / 128, Bz * Hh);
        k_mm<1><<<g, 256, SMEM_MM>>>(
            ph, pl, vth, vtl, nullptr, aoh, aol, Ss, Hh * Dd,
            (long long)Hh * Ss * Ss, (long long)Ss * Ss,
            (long long)KVh * Dd * Ss, (long long)Dd * Ss,
            (long long)Ss * Hh * Dd, (long long)Dd,
            Hh, Hh / KVh, 2);
    }

    // 8) out = attnout @ o_w^T -> d_out [4096,2048] fp32
    {
        dim3 g(HID / 128, MROWS / 128, 1);
        k_mm<0><<<g, 256, SMEM_MM>>>(aoh, aol, owh, owl, out, nullptr, nullptr,
                                     Hh * Dd, HID, 0, 0, 0, 0, 0, 0, 1, 1, 0);
    }
}